// round 10
// baseline (speedup 1.0000x reference)
#include <cuda_runtime.h>
#include <math.h>

// ============================================================================
// ThermoQuantizer, single fused kernel. Round 10: depth-2 load pipeline.
//
// out = (1-p)*x + p * mean_c * f(x / mean_c)  ==  mean_c * G(u),
//   u = (x/mean_c)*TSCALE + TOFF,  G tabulated in P/Q form with the lerp
//   folded in:  G(u) = P_j + u*Q_j,  j=(int)u  (6 ops per element).
//
// TN=768 over [-21,21]: data xn in [-8,8] -> u in [238,530], no clamps.
// Group abs-mean via fixed-point redux.sync.add.s32 (1 instr).
// Pipeline: three pair-buffers A/B/C; iteration k issues loads for k+2,
// processes A, rotates. Loads stay outstanding ~the whole iteration,
// doubling in-flight DRAM bytes vs the depth-1 prefetch (47% DRAM -> ~65%).
// ============================================================================

#define TN      768
#define THALF   21.0f
#define TSCALE  ((float)TN / (2.0f * THALF))
#define TOFF    ((float)TN * 0.5f)
#define FIXS    262144.0f   // 2^18 fixed-point scale for the warp reduction

__device__ __forceinline__ float rcp_approx(float x) {
    float r;
    asm("rcp.approx.f32 %0, %1;" : "=f"(r) : "f"(x));
    return r;
}
__device__ __forceinline__ int warp_sum_i(int x) {
    int r;
    asm("redux.sync.add.s32 %0, %1, 0xffffffff;" : "=r"(r) : "r"(x));
    return r;
}
__device__ __forceinline__ float4 ldcs4(const float4* p) {
    float4 v;
    asm("ld.global.cs.v4.f32 {%0,%1,%2,%3}, [%4];"
        : "=f"(v.x), "=f"(v.y), "=f"(v.z), "=f"(v.w) : "l"(p));
    return v;
}
__device__ __forceinline__ void stcs4(float4* p, float4 v) {
    asm("st.global.cs.v4.f32 [%0], {%1,%2,%3,%4};"
        :: "l"(p), "f"(v.x), "f"(v.y), "f"(v.z), "f"(v.w) : "memory");
}

__global__ __launch_bounds__(512, 2)
void tq_fused(const float4* __restrict__ x4, float4* __restrict__ out4,
              const float* __restrict__ cb, const float* __restrict__ pressure,
              const float* __restrict__ temp, int ngroups) {
    __shared__ float  vals[TN + 1];
    __shared__ float2 tbl[TN];     // (P, Q): G = P + u*Q, lerp folded in

    int lane = threadIdx.x & 31;
    int w    = blockIdx.x * 16 + (threadIdx.x >> 5);
    int W    = gridDim.x * 16;
    int step = 2 * W;                        // groups per pipeline stage

    int g = w * 2;                           // ngroups even => g+1 valid
    bool haveA = g < ngroups;
    bool haveB = g + step < ngroups;
    const float4* src = x4   + (g << 5) + lane;
    float4*       dst = out4 + (g << 5) + lane;
    const long sstep = (long)step << 5;      // float4 elems per stage

    // Stage A and B loads issued BEFORE the table build (latency hidden
    // behind the MUFU-heavy build).
    float4 a0, a1, b0, b1;
    if (haveA) { a0 = ldcs4(src);          a1 = ldcs4(src + 32); }
    if (haveB) { b0 = ldcs4(src + sstep);  b1 = ldcs4(src + sstep + 32); }

    float p   = *pressure;
    float omp = 1.0f - p;

    // ---- Phase 1: build raw f table ----
    {
        float T = *temp + 1e-6f;
        float invT = 1.0f / T;
        float c[16];
#pragma unroll
        for (int i = 0; i < 16; i++) c[i] = cb[i];

        for (int j = threadIdx.x; j < TN + 1; j += 512) {
            float xn = -THALF + (float)j * (2.0f * THALF / (float)TN);
            float m = -3.4e38f;
            float lg[16];
#pragma unroll
            for (int i = 0; i < 16; i++) {
                float d = xn - c[i];
                lg[i] = -(d * d) * invT;
                m = fmaxf(m, lg[i]);
            }
            float sw = 0.0f, sc = 0.0f;
#pragma unroll
            for (int i = 0; i < 16; i++) {
                float wgt = __expf(lg[i] - m);
                sw += wgt;
                sc += wgt * c[i];
            }
            vals[j] = sc / sw;
        }
    }
    __syncthreads();
    // fold lerp into P/Q: G(u) = omp*(u-TOFF)/TSCALE + p*f_interp(u)
    for (int j = threadIdx.x; j < TN; j += 512) {
        float d  = vals[j + 1] - vals[j];
        float Qp = p * d + omp * (1.0f / TSCALE);
        float Pp = p * (vals[j] - (float)j * d) - omp * (TOFF / TSCALE);
        tbl[j] = make_float2(Pp, Qp);
    }
    __syncthreads();

    if (!haveA) return;

    // ---- Phase 2: depth-2 pipelined stream ----
    while (true) {
        // issue loads for stage k+2
        bool haveC = g + 2 * step < ngroups;
        float4 c0, c1;
        if (haveC) {
            c0 = ldcs4(src + 2 * sstep);
            c1 = ldcs4(src + 2 * sstep + 32);
        }

        // process stage A
        float s0 = fabsf(a0.x) + fabsf(a0.y) + fabsf(a0.z) + fabsf(a0.w);
        float s1 = fabsf(a1.x) + fabsf(a1.y) + fabsf(a1.z) + fabsf(a1.w);
        int i0 = warp_sum_i(__float2int_rn(s0 * FIXS));
        int i1 = warp_sum_i(__float2int_rn(s1 * FIXS));
        float mean0 = fmaxf((float)i0 * (1.0f / (FIXS * 128.0f)), 1e-5f);
        float mean1 = fmaxf((float)i1 * (1.0f / (FIXS * 128.0f)), 1e-5f);
        float ks0 = rcp_approx(mean0) * TSCALE;
        float ks1 = rcp_approx(mean1) * TSCALE;

        float4 o0, o1;
#define LOOKUP(OUT, VIN, KS, MEAN)                                            \
        {                                                                     \
            float u = fmaf((VIN), (KS), TOFF);                                \
            int jx = (int)u;                                                  \
            float2 t = tbl[jx];                                               \
            (OUT) = (MEAN) * fmaf(u, t.y, t.x);                               \
        }
        LOOKUP(o0.x, a0.x, ks0, mean0)
        LOOKUP(o1.x, a1.x, ks1, mean1)
        LOOKUP(o0.y, a0.y, ks0, mean0)
        LOOKUP(o1.y, a1.y, ks1, mean1)
        LOOKUP(o0.z, a0.z, ks0, mean0)
        LOOKUP(o1.z, a1.z, ks1, mean1)
        LOOKUP(o0.w, a0.w, ks0, mean0)
        LOOKUP(o1.w, a1.w, ks1, mean1)
#undef LOOKUP

        stcs4(dst, o0);
        stcs4(dst + 32, o1);

        if (!haveB) break;
        // rotate pipeline
        a0 = b0; a1 = b1;
        b0 = c0; b1 = c1;
        haveB = haveC;
        g += step; src += sstep; dst += sstep;
    }
}

extern "C" void kernel_launch(void* const* d_in, const int* in_sizes, int n_in,
                              void* d_out, int out_size) {
    const float* x        = (const float*)d_in[0];
    const float* cb       = (const float*)d_in[1];
    const float* pressure = (const float*)d_in[2];
    const float* temp     = (const float*)d_in[3];

    int n = in_sizes[0];
    int ngroups = n / 128;

    int blocks = 148 * 2;   // persistent grid-stride, 2 blocks/SM
    tq_fused<<<blocks, 512>>>((const float4*)x, (float4*)d_out,
                              cb, pressure, temp, ngroups);
}

// round 11
// speedup vs baseline: 1.1347x; 1.1347x over previous
#include <cuda_runtime.h>
#include <cuda_fp16.h>
#include <math.h>

// ============================================================================
// ThermoQuantizer, single fused kernel. Round 11: fp16x2 table -> LDS.32.
//
// out = (1-p)*x + p * mean_c * f(x/mean_c)  ==  mean_c * G(xn)
// G tabulated at TN=768 nodes over [-21,21] as half2(A_j, B_j):
//   A_j = G(node j), B_j = G(node j+1) - G(node j)
//   out = mean * (A_j + fr*B_j),  j = floor(u), fr = u - j, u = xn*TSCALE+TOFF
// One 4-byte LDS per element (32 bank-requests/warp vs 64 for float2),
// cutting the smem conflict phases that cap the l1tex pipe.
// floor/frac via the 2^23 trick (no F2I/I2F latency).
// Group abs-mean via fixed-point redux.sync.add.s32.
// ============================================================================

#define TN      768
#define THALF   21.0f
#define TSCALE  ((float)TN / (2.0f * THALF))
#define TOFF    ((float)TN * 0.5f)
#define FIXS    262144.0f                  // 2^18 fixed-point reduction scale
#define C23     8388608.0f                 // 2^23
#define BIGOFF  (TOFF - 0.5f + C23)        // fma addend for floor-extract
#define K2      (TOFF + C23)               // for fr reconstruction
#define IBASE   0x4B000000                 // bit pattern of 2^23

__device__ __forceinline__ float rcp_approx(float x) {
    float r;
    asm("rcp.approx.f32 %0, %1;" : "=f"(r) : "f"(x));
    return r;
}
__device__ __forceinline__ int warp_sum_i(int x) {
    int r;
    asm("redux.sync.add.s32 %0, %1, 0xffffffff;" : "=r"(r) : "r"(x));
    return r;
}
__device__ __forceinline__ float4 ldcs4(const float4* p) {
    float4 v;
    asm("ld.global.cs.v4.f32 {%0,%1,%2,%3}, [%4];"
        : "=f"(v.x), "=f"(v.y), "=f"(v.z), "=f"(v.w) : "l"(p));
    return v;
}
__device__ __forceinline__ void stcs4(float4* p, float4 v) {
    asm("st.global.cs.v4.f32 [%0], {%1,%2,%3,%4};"
        :: "l"(p), "f"(v.x), "f"(v.y), "f"(v.z), "f"(v.w) : "memory");
}

__global__ __launch_bounds__(512, 2)
void tq_fused(const float4* __restrict__ x4, float4* __restrict__ out4,
              const float* __restrict__ cb, const float* __restrict__ pressure,
              const float* __restrict__ temp, int ngroups) {
    __shared__ float   vals[TN + 1];
    __shared__ __half2 tbl[TN];            // (A, B) per node, fp16

    int lane = threadIdx.x & 31;
    int w    = blockIdx.x * 16 + (threadIdx.x >> 5);
    int W    = gridDim.x * 16;
    int step = 2 * W;

    // First pair's loads before the table build (latency hidden by MUFU work).
    int g = w * 2;                          // ngroups even => g+1 valid
    bool have = g < ngroups;
    const float4* src = x4   + (g << 5) + lane;
    float4*       dst = out4 + (g << 5) + lane;
    const long sstep = (long)step << 5;

    float4 v0, v1;
    if (have) {
        v0 = ldcs4(src);
        v1 = ldcs4(src + 32);
    }

    float p   = *pressure;
    float omp = 1.0f - p;

    // ---- Phase 1: tabulate G(xn) = omp*xn + p*f(xn) at TN+1 nodes ----
    {
        float T = *temp + 1e-6f;
        float invT = 1.0f / T;
        float c[16];
#pragma unroll
        for (int i = 0; i < 16; i++) c[i] = cb[i];

        for (int j = threadIdx.x; j < TN + 1; j += 512) {
            float xn = -THALF + (float)j * (2.0f * THALF / (float)TN);
            float m = -3.4e38f;
            float lg[16];
#pragma unroll
            for (int i = 0; i < 16; i++) {
                float d = xn - c[i];
                lg[i] = -(d * d) * invT;
                m = fmaxf(m, lg[i]);
            }
            float sw = 0.0f, sc = 0.0f;
#pragma unroll
            for (int i = 0; i < 16; i++) {
                float wgt = __expf(lg[i] - m);
                sw += wgt;
                sc += wgt * c[i];
            }
            vals[j] = omp * xn + p * (sc / sw);   // G at node j
        }
    }
    __syncthreads();
    for (int j = threadIdx.x; j < TN; j += 512)
        tbl[j] = __floats2half2_rn(vals[j], vals[j + 1] - vals[j]);
    __syncthreads();

    if (!have) return;

    // ---- Phase 2: stream; 2 groups per warp-iter, next pair prefetched ----
    while (true) {
        int gn = g + step;
        bool more = gn < ngroups;
        float4 n0, n1;
        if (more) {
            n0 = ldcs4(src + sstep);
            n1 = ldcs4(src + sstep + 32);
        }

        // fixed-point single-instruction warp reductions
        float a0 = fabsf(v0.x) + fabsf(v0.y) + fabsf(v0.z) + fabsf(v0.w);
        float a1 = fabsf(v1.x) + fabsf(v1.y) + fabsf(v1.z) + fabsf(v1.w);
        int i0 = warp_sum_i(__float2int_rn(a0 * FIXS));
        int i1 = warp_sum_i(__float2int_rn(a1 * FIXS));
        float mean0 = fmaxf((float)i0 * (1.0f / (FIXS * 128.0f)), 1e-5f);
        float mean1 = fmaxf((float)i1 * (1.0f / (FIXS * 128.0f)), 1e-5f);
        float ks0 = rcp_approx(mean0) * TSCALE;
        float ks1 = rcp_approx(mean1) * TSCALE;

        float4 o0, o1;
#define LOOKUP(OUT, VIN, KS, MEAN)                                            \
        {                                                                     \
            float big = fmaf((VIN), (KS), BIGOFF);    /* 2^23 + floor(u) */   \
            int   jx  = __float_as_int(big) - IBASE;  /* floor(u) */          \
            float s   = K2 - big;                     /* TOFF - jf */         \
            float fr  = fmaf((VIN), (KS), s);         /* u - floor(u) */      \
            float2 ab = __half22float2(tbl[jx]);                              \
            (OUT) = (MEAN) * fmaf(fr, ab.y, ab.x);                            \
        }
        LOOKUP(o0.x, v0.x, ks0, mean0)
        LOOKUP(o1.x, v1.x, ks1, mean1)
        LOOKUP(o0.y, v0.y, ks0, mean0)
        LOOKUP(o1.y, v1.y, ks1, mean1)
        LOOKUP(o0.z, v0.z, ks0, mean0)
        LOOKUP(o1.z, v1.z, ks1, mean1)
        LOOKUP(o0.w, v0.w, ks0, mean0)
        LOOKUP(o1.w, v1.w, ks1, mean1)
#undef LOOKUP

        stcs4(dst, o0);
        stcs4(dst + 32, o1);

        if (!more) break;
        v0 = n0; v1 = n1; g = gn;
        src += sstep; dst += sstep;
    }
}

extern "C" void kernel_launch(void* const* d_in, const int* in_sizes, int n_in,
                              void* d_out, int out_size) {
    const float* x        = (const float*)d_in[0];
    const float* cb       = (const float*)d_in[1];
    const float* pressure = (const float*)d_in[2];
    const float* temp     = (const float*)d_in[3];

    int n = in_sizes[0];
    int ngroups = n / 128;

    int blocks = 148 * 2;   // persistent grid-stride, 2 blocks/SM
    tq_fused<<<blocks, 512>>>((const float4*)x, (float4*)d_out,
                              cb, pressure, temp, ngroups);
}